// round 4
// baseline (speedup 1.0000x reference)
#include <cuda_runtime.h>
#include <cstdint>

// ---------------------------------------------------------------------------
// AnnularPatchEmbed: out[b,c,j] = fc( sum_{p in ring c} x[b,p] * W[:,p] )
// Rings computed analytically (exact integer d^2 thresholds, identical to the
// reference's dist-vs-7i comparisons). Segmented SGEMM over ~39.4K masked
// pixels with a 3-stage cp.async pipeline and f32x2 packed FMAs.
// ---------------------------------------------------------------------------

#define IMGSZ 224
#define NPIX  50176
#define NB    64
#define ND    256
#define CK    288        // pixels per GEMM chunk (ring-aligned)
#define MAXC  192        // upper bound on chunk count (actual ~150)

#define FMA2(c, a, b) asm("fma.rn.f32x2 %0, %1, %2, %0;" : "+l"(c) : "l"(a), "l"(b))
#define PACK2(p, f)   asm("mov.b64 %0, {%1, %1};" : "=l"(p) : "f"(f))
#define UNPACK2(lo, hi, c) asm("mov.b64 {%0, %1}, %2;" : "=f"(lo), "=f"(hi) : "l"(c))
#define CP4(dst, src, sz) \
    asm volatile("cp.async.ca.shared.global [%0], [%1], 4, %2;" \
                 :: "r"(dst), "l"(src), "r"(sz))
#define CP_COMMIT() asm volatile("cp.async.commit_group;" ::: "memory")
#define CP_WAIT1()  asm volatile("cp.async.wait_group 1;" ::: "memory")

// ------------------------- device scratch (static, no allocs) --------------
__device__ int   g_ringChunkStart[17];
__device__ int   g_chunkStart[MAXC];
__device__ int   g_chunkLen[MAXC];
__device__ int   g_numChunks;
__device__ int   g_perm[NPIX];
__device__ float g_partial[(size_t)MAXC * NB * ND];   // 12.6 MB

// Exact ring id from squared distance. Boundaries dist>=7i are exact in
// integer: dist >= 7i  <=>  d2 >= 49*i*i.
__device__ __forceinline__ int ring_of(int d2) {
    if (d2 >= 12544) return 16;           // dist >= 112 -> unmasked
    int r = 0;
    #pragma unroll
    for (int i = 1; i < 16; i++) r += (d2 >= 49 * i * i);
    return r;
}

// ------------------------- 1) fused prep: count + scan + scatter -----------
// Single block, 1024 threads (32 warps; warp w owns rows 7w..7w+6).
__global__ void __launch_bounds__(1024) k_prep() {
    __shared__ int sRowCnt[IMGSZ * 17];   // 15.2 KB
    __shared__ int sRowBase[IMGSZ * 16];  // 14.3 KB
    __shared__ int sOff[17];
    __shared__ int sCnt[32][17];

    int tid = threadIdx.x, w = tid >> 5, lane = tid & 31;

    for (int i = tid; i < IMGSZ * 17; i += 1024) sRowCnt[i] = 0;
    __syncthreads();

    // phase 1: per-row ring histograms (pure integer math, no DRAM reads)
    #pragma unroll 1
    for (int ry = 0; ry < 7; ry++) {
        int y = w * 7 + ry;
        int dy = y - 112, dy2 = dy * dy;
        #pragma unroll 1
        for (int g = 0; g < 7; g++) {
            int x = g * 32 + lane, dx = x - 112;
            int r = ring_of(dx * dx + dy2);
            atomicAdd(&sRowCnt[y * 17 + r], 1);
        }
    }
    __syncthreads();

    // phase 2a: ring totals (warp w<16 owns ring w)
    int v[7];
    if (w < 16) {
        int tot = 0;
        #pragma unroll
        for (int g = 0; g < 7; g++) {
            v[g] = sRowCnt[(g * 32 + lane) * 17 + w];
            tot += v[g];
        }
        #pragma unroll
        for (int d = 16; d; d >>= 1) tot += __shfl_xor_sync(~0u, tot, d);
        if (lane == 0) sOff[w] = tot;
    }
    __syncthreads();

    if (tid == 0) {
        int run = 0;
        #pragma unroll
        for (int c = 0; c < 16; c++) { int t = sOff[c]; sOff[c] = run; run += t; }
        sOff[16] = run;
        int nc = 0;
        for (int c = 0; c < 16; c++) {
            g_ringChunkStart[c] = nc;
            int n = sOff[c + 1] - sOff[c], base = sOff[c];
            for (int s = 0; s < n && nc < MAXC; s += CK) {
                g_chunkStart[nc] = base + s;
                g_chunkLen[nc]   = (n - s < CK) ? (n - s) : CK;
                nc++;
            }
        }
        g_ringChunkStart[16] = nc;
        g_numChunks = nc;
    }
    __syncthreads();

    // phase 2b: row bases (exclusive scan of row counts per ring)
    if (w < 16) {
        int carry = sOff[w];
        #pragma unroll
        for (int g = 0; g < 7; g++) {
            int xv = v[g], incl = xv;
            #pragma unroll
            for (int d = 1; d < 32; d <<= 1) {
                int nbr = __shfl_up_sync(~0u, incl, d);
                if (lane >= d) incl += nbr;
            }
            sRowBase[(g * 32 + lane) * 16 + w] = carry + incl - xv;
            carry += __shfl_sync(~0u, incl, 31);
        }
    }
    __syncthreads();

    // phase 3: deterministic scatter (row-major within ring)
    unsigned lt = (lane == 0) ? 0u : ((1u << lane) - 1u);
    #pragma unroll 1
    for (int ry = 0; ry < 7; ry++) {
        int y = w * 7 + ry;
        int dy = y - 112, dy2 = dy * dy;
        if (lane < 17) sCnt[w][lane] = 0;
        __syncwarp();
        #pragma unroll 1
        for (int g = 0; g < 7; g++) {
            int x = g * 32 + lane, dx = x - 112;
            int r = ring_of(dx * dx + dy2);
            unsigned same = __match_any_sync(0xffffffffu, r);
            int rank = __popc(same & lt);
            int base = sCnt[w][r];
            __syncwarp();
            if (rank == 0) sCnt[w][r] = base + __popc(same);
            __syncwarp();
            if (r < 16) g_perm[sRowBase[y * 16 + r] + base + rank] = y * IMGSZ + x;
        }
    }
}

// ------------------------- 2) main segmented SGEMM -------------------------
// Grid (MAXC, 2). CTA = one 288-pixel chunk x one 128-wide d half.
// 64(b) x 128(d) tile, 256 threads. 3-stage cp.async pipeline, KTILE=16,
// f32x2 packed accumulators (4 b-pairs x 4 d per thread).
__global__ void __launch_bounds__(256, 2)
k_gemm(const float* __restrict__ X, const float* __restrict__ W) {
    int ch = blockIdx.x;
    if (ch >= g_numChunks) return;
    int d0     = blockIdx.y * 128;
    int kStart = g_chunkStart[ch];
    int kLen   = g_chunkLen[ch];

    __shared__ __align__(16) float xs[3][16 * 68];
    __shared__ __align__(16) float ws[3][16 * 132];
    __shared__ int pSm[CK];

    int tid = threadIdx.x;
    for (int i = tid; i < CK; i += 256)
        pSm[i] = (i < kLen) ? g_perm[kStart + i] : 0;   // clamp; sz=0 masks it
    __syncthreads();

    int tb = tid >> 5;       // 0..7  -> 8 b-rows each (4 pairs)
    int td = tid & 31;       // 0..31 -> 4 d-cols each
    int numTiles = (kLen + 15) >> 4;

    uint32_t xsA = (uint32_t)__cvta_generic_to_shared(&xs[0][0]);
    uint32_t wsA = (uint32_t)__cvta_generic_to_shared(&ws[0][0]);

    auto issueTile = [&](int t) {
        if (t < numTiles) {
            int k0 = t << 4;
            int s  = t % 3;
            #pragma unroll
            for (int j = 0; j < 4; j++) {
                int i = tid + j * 256;
                int b = i >> 4, kk = i & 15;
                int gk = k0 + kk;
                int sz = (gk < kLen) ? 4 : 0;
                const float* src = X + b * NPIX + pSm[gk];
                uint32_t dst = xsA + (uint32_t)(s * (16 * 68) + kk * 68 + b) * 4u;
                CP4(dst, src, sz);
            }
            #pragma unroll
            for (int j = 0; j < 8; j++) {
                int i = tid + j * 256;
                int d = i >> 4, kk = i & 15;
                int gk = k0 + kk;
                int sz = (gk < kLen) ? 4 : 0;
                const float* src = W + (size_t)(d0 + d) * NPIX + pSm[gk];
                uint32_t dst = wsA + (uint32_t)(s * (16 * 132) + kk * 132 + d) * 4u;
                CP4(dst, src, sz);
            }
        }
        CP_COMMIT();
    };

    unsigned long long acc[4][4];     // [b-pair][d]
    #pragma unroll
    for (int i = 0; i < 4; i++)
        #pragma unroll
        for (int j = 0; j < 4; j++) acc[i][j] = 0ULL;

    issueTile(0);
    issueTile(1);

    for (int t = 0; t < numTiles; t++) {
        CP_WAIT1();                 // tile t resident (t+1 may be in flight)
        __syncthreads();            // all warps see it; stage (t-1)%3 free
        issueTile(t + 2);           // refill stage (t+2)%3 == (t-1)%3

        int s = t % 3;
        const float* xb = &xs[s][0];
        const float* wb = &ws[s][0];
        #pragma unroll
        for (int kk = 0; kk < 16; kk++) {
            const float* xrow = xb + kk * 68 + tb * 8;
            ulonglong2 xa = *(const ulonglong2*)xrow;         // b-pairs 0,1
            ulonglong2 xc = *(const ulonglong2*)(xrow + 4);   // b-pairs 2,3
            float4 wv = *(const float4*)(wb + kk * 132 + td * 4);
            unsigned long long wp0, wp1, wp2, wp3;
            PACK2(wp0, wv.x); PACK2(wp1, wv.y); PACK2(wp2, wv.z); PACK2(wp3, wv.w);
            FMA2(acc[0][0], xa.x, wp0); FMA2(acc[0][1], xa.x, wp1);
            FMA2(acc[0][2], xa.x, wp2); FMA2(acc[0][3], xa.x, wp3);
            FMA2(acc[1][0], xa.y, wp0); FMA2(acc[1][1], xa.y, wp1);
            FMA2(acc[1][2], xa.y, wp2); FMA2(acc[1][3], xa.y, wp3);
            FMA2(acc[2][0], xc.x, wp0); FMA2(acc[2][1], xc.x, wp1);
            FMA2(acc[2][2], xc.x, wp2); FMA2(acc[2][3], xc.x, wp3);
            FMA2(acc[3][0], xc.y, wp0); FMA2(acc[3][1], xc.y, wp1);
            FMA2(acc[3][2], xc.y, wp2); FMA2(acc[3][3], xc.y, wp3);
        }
    }

    // unpack + write partials (float4 per b-row)
    size_t base = (size_t)ch * (NB * ND);
    #pragma unroll
    for (int bp = 0; bp < 4; bp++) {
        float lo0, hi0, lo1, hi1, lo2, hi2, lo3, hi3;
        UNPACK2(lo0, hi0, acc[bp][0]);
        UNPACK2(lo1, hi1, acc[bp][1]);
        UNPACK2(lo2, hi2, acc[bp][2]);
        UNPACK2(lo3, hi3, acc[bp][3]);
        int b0 = tb * 8 + bp * 2;
        float4 vlo = make_float4(lo0, lo1, lo2, lo3);
        float4 vhi = make_float4(hi0, hi1, hi2, hi3);
        *(float4*)&g_partial[base + (size_t)b0 * ND + d0 + td * 4] = vlo;
        *(float4*)&g_partial[base + (size_t)(b0 + 1) * ND + d0 + td * 4] = vhi;
    }
}

// ------------------------- 3) fused chunk-reduce + fc (256->192) -----------
// Grid 64 (one block per b), 256 threads. Reduce: thread = one d over all c.
// Then fc with f32x2 packed over ring-pairs.
__global__ void __launch_bounds__(256)
k_fc(const float* __restrict__ fcw, const float* __restrict__ fcb,
     float* __restrict__ out) {
    __shared__ __align__(16) float tok[256 * 20];   // [d][c] padded to 20
    __shared__ int cs[17];

    int b = blockIdx.x, tid = threadIdx.x;
    if (tid < 17) cs[tid] = g_ringChunkStart[tid];
    __syncthreads();

    // parallel reduction over chunks: coalesced across d = tid
    {
        size_t brow = (size_t)b * ND + tid;
        #pragma unroll 1
        for (int c = 0; c < 16; c++) {
            int c0 = cs[c], c1 = cs[c + 1];
            float s0 = 0.f, s1 = 0.f;
            int ch = c0;
            for (; ch + 1 < c1; ch += 2) {
                s0 += g_partial[(size_t)ch * (NB * ND) + brow];
                s1 += g_partial[(size_t)(ch + 1) * (NB * ND) + brow];
            }
            if (ch < c1) s0 += g_partial[(size_t)ch * (NB * ND) + brow];
            tok[tid * 20 + c] = s0 + s1;
        }
    }
    __syncthreads();

    if (tid < 192) {
        int j = tid;
        unsigned long long acc[8];
        #pragma unroll
        for (int q = 0; q < 8; q++) acc[q] = 0ULL;

        const float4* fw4 = (const float4*)(fcw + (size_t)j * ND);
        #pragma unroll 4
        for (int d4 = 0; d4 < 64; d4++) {
            float4 wv = fw4[d4];
            #pragma unroll
            for (int s = 0; s < 4; s++) {
                int d = d4 * 4 + s;
                float w = (s == 0) ? wv.x : (s == 1) ? wv.y : (s == 2) ? wv.z : wv.w;
                unsigned long long wp;
                PACK2(wp, w);
                const ulonglong2* tp = (const ulonglong2*)&tok[d * 20];
                ulonglong2 t0 = tp[0], t1 = tp[1], t2 = tp[2], t3 = tp[3];
                FMA2(acc[0], t0.x, wp); FMA2(acc[1], t0.y, wp);
                FMA2(acc[2], t1.x, wp); FMA2(acc[3], t1.y, wp);
                FMA2(acc[4], t2.x, wp); FMA2(acc[5], t2.y, wp);
                FMA2(acc[6], t3.x, wp); FMA2(acc[7], t3.y, wp);
            }
        }
        float bias = fcb[j];
        #pragma unroll
        for (int q = 0; q < 8; q++) {
            float lo, hi;
            UNPACK2(lo, hi, acc[q]);
            out[((size_t)b * 16 + 2 * q) * 192 + j]     = lo + bias;
            out[((size_t)b * 16 + 2 * q + 1) * 192 + j] = hi + bias;
        }
    }
}

// ---------------------------------------------------------------------------
extern "C" void kernel_launch(void* const* d_in, const int* in_sizes, int n_in,
                              void* d_out, int out_size) {
    const float* x   = (const float*)d_in[0];  // [64, 224, 224]
    const float* tw  = (const float*)d_in[1];  // [256, 1, 224, 224]
    const float* fcw = (const float*)d_in[2];  // [192, 256]
    const float* fcb = (const float*)d_in[3];  // [192]
    // d_in[4] (masks) unused: rings derived analytically (exact).
    float* out = (float*)d_out;                // [64, 16, 192]

    k_prep<<<1, 1024>>>();
    k_gemm<<<dim3(MAXC, 2), 256>>>(x, tw);
    k_fc<<<64, 256>>>(fcw, fcb, out);
}

// round 6
// speedup vs baseline: 1.2707x; 1.2707x over previous
#include <cuda_runtime.h>
#include <cstdint>
#include <cmath>

// ---------------------------------------------------------------------------
// AnnularPatchEmbed: out[b,c,j] = fc( sum_{p in ring c} x[b,p] * W[:,p] )
// Rings derived in closed form (exact integer sqrt intervals per row).
// Segmented SGEMM (cp.async 3-stage, f32x2 FMA) -> parallel reduce -> fc.
// ---------------------------------------------------------------------------

#define IMGSZ 224
#define NPIX  50176
#define NB    64
#define ND    256
#define CK    288        // pixels per GEMM chunk (ring-aligned)
#define MAXC  192        // upper bound on chunk count (actual ~145)

#define FMA2(c, a, b) asm("fma.rn.f32x2 %0, %1, %2, %0;" : "+l"(c) : "l"(a), "l"(b))
#define PACK2(p, f)   asm("mov.b64 %0, {%1, %1};" : "=l"(p) : "f"(f))
#define UNPACK2(lo, hi, c) asm("mov.b64 {%0, %1}, %2;" : "=f"(lo), "=f"(hi) : "l"(c))
#define CP4(dst, src, sz) \
    asm volatile("cp.async.ca.shared.global [%0], [%1], 4, %2;" \
                 :: "r"(dst), "l"(src), "r"(sz))
#define CP_COMMIT() asm volatile("cp.async.commit_group;" ::: "memory")
#define CP_WAIT1()  asm volatile("cp.async.wait_group 1;" ::: "memory")

// ------------------------- device scratch (static, no allocs) --------------
__device__ int   g_rowBase[IMGSZ * 16];
__device__ int   g_ringChunkStart[17];
__device__ int   g_chunkStart[MAXC];
__device__ int   g_chunkLen[MAXC];
__device__ int   g_numChunks;
__device__ int   g_perm[NPIX];
__device__ float g_partial[(size_t)MAXC * NB * ND];   // 12.6 MB
__device__ float g_tok[(size_t)NB * 16 * ND];         // 1 MB

// largest m >= 0 with m*m < t (requires t >= 1)
__device__ __forceinline__ int isqrt_lt(int t) {
    int m = (int)sqrtf((float)t);
    if (m > 120) m = 120;
    while (m > 0 && m * m >= t) m--;
    while ((m + 1) * (m + 1) < t) m++;
    return m;
}

// ring r occupies |dx| in [a, b] on a row with dy^2 = dy2 (empty if a > b).
// Exact: dist >= 7i  <=>  d2 >= 49 i^2 (float sqrt thresholds can't misround:
// gap to 7i is >= 1/224 >> ulp).
__device__ __forceinline__ void ring_interval(int r, int dy2, int& a, int& b) {
    int t_lo = 49 * r * r - dy2;
    int t_hi = 49 * (r + 1) * (r + 1) - dy2;
    if (t_hi < 1) { a = 1; b = 0; return; }
    b = isqrt_lt(t_hi);                          // largest |dx| with dx^2 < t_hi
    a = (t_lo < 1) ? 0 : (isqrt_lt(t_lo) + 1);   // smallest |dx| with dx^2 >= t_lo
}
__device__ __forceinline__ int interval_count(int a, int b) {
    if (a > b) return 0;
    return (a == 0) ? (2 * b + 1) : (2 * (b - a + 1));
}

// ------------------------- 1) prep: counts, scans, chunk list --------------
// Single block, 256 threads; all O(1)-per-(row,ring) arithmetic.
__global__ void __launch_bounds__(256) k_prep() {
    __shared__ int sCnt[IMGSZ * 16];   // per-(row,ring) counts
    __shared__ int sPart[256];
    __shared__ int sOff[17];

    int tid = threadIdx.x;

    for (int i = tid; i < IMGSZ * 16; i += 256) {
        int y = i >> 4, r = i & 15;
        int dy = y - 112, a, b;
        ring_interval(r, dy * dy, a, b);
        sCnt[i] = interval_count(a, b);
    }
    __syncthreads();

    // ring totals: thread (r*16+sub) sums rows sub, sub+16, ...
    {
        int r = tid >> 4, sub = tid & 15;
        int part = 0;
        for (int y = sub; y < IMGSZ; y += 16) part += sCnt[y * 16 + r];
        sPart[tid] = part;
    }
    __syncthreads();
    if (tid < 16) {
        int s = 0;
        #pragma unroll
        for (int k = 0; k < 16; k++) s += sPart[tid * 16 + k];
        sOff[tid] = s;
    }
    __syncthreads();
    if (tid == 0) {
        int run = 0;
        #pragma unroll
        for (int c = 0; c < 16; c++) { int t = sOff[c]; sOff[c] = run; run += t; }
        sOff[16] = run;
        int nc = 0;
        for (int c = 0; c < 16; c++) {
            g_ringChunkStart[c] = nc;
            int n = sOff[c + 1] - sOff[c], base = sOff[c];
            for (int s = 0; s < n && nc < MAXC; s += CK) {
                g_chunkStart[nc] = base + s;
                g_chunkLen[nc]   = (n - s < CK) ? (n - s) : CK;
                nc++;
            }
        }
        g_ringChunkStart[16] = nc;
        g_numChunks = nc;
    }
    __syncthreads();

    // row bases: warp w scans rings w and w+8 over rows (shuffle scan)
    int w = tid >> 5, lane = tid & 31;
    #pragma unroll
    for (int it = 0; it < 2; it++) {
        int r = w + 8 * it;
        int carry = sOff[r];
        #pragma unroll
        for (int g = 0; g < 7; g++) {
            int y = g * 32 + lane;
            int xv = sCnt[y * 16 + r], incl = xv;
            #pragma unroll
            for (int d = 1; d < 32; d <<= 1) {
                int nbr = __shfl_up_sync(~0u, incl, d);
                if (lane >= d) incl += nbr;
            }
            g_rowBase[y * 16 + r] = carry + incl - xv;
            carry += __shfl_sync(~0u, incl, 31);
        }
    }
}

// ------------------------- 2) scatter: closed-form perm --------------------
// Grid 14 x 256: one thread per (row, ring); writes its contiguous x-runs.
__global__ void __launch_bounds__(256) k_scatter() {
    int idx = blockIdx.x * 256 + threadIdx.x;
    if (idx >= IMGSZ * 16) return;
    int y = idx >> 4, r = idx & 15;
    int dy = y - 112, a, b;
    ring_interval(r, dy * dy, a, b);
    if (a > b) return;
    int base = g_rowBase[y * 16 + r];
    int rowp = y * IMGSZ + 112;
    if (a == 0) {
        for (int dx = -b; dx <= b; dx++) g_perm[base++] = rowp + dx;
    } else {
        for (int dx = -b; dx <= -a; dx++) g_perm[base++] = rowp + dx;
        for (int dx = a; dx <= b; dx++)   g_perm[base++] = rowp + dx;
    }
}

// ------------------------- 3) main segmented SGEMM -------------------------
// Grid (MAXC, 2). CTA = one 288-pixel chunk x one 128-wide d half.
// 64(b) x 128(d) tile, 256 threads. 3-stage cp.async pipeline, KTILE=16,
// f32x2 packed accumulators (4 b-pairs x 4 d per thread).
__global__ void __launch_bounds__(256, 2)
k_gemm(const float* __restrict__ X, const float* __restrict__ W) {
    int ch = blockIdx.x;
    if (ch >= g_numChunks) return;
    int d0     = blockIdx.y * 128;
    int kStart = g_chunkStart[ch];
    int kLen   = g_chunkLen[ch];

    __shared__ __align__(16) float xs[3][16 * 68];
    __shared__ __align__(16) float ws[3][16 * 132];
    __shared__ int pSm[CK];

    int tid = threadIdx.x;
    for (int i = tid; i < CK; i += 256)
        pSm[i] = (i < kLen) ? g_perm[kStart + i] : 0;   // clamp; sz=0 masks it
    __syncthreads();

    int tb = tid >> 5;       // 0..7  -> 8 b-rows each (4 pairs)
    int td = tid & 31;       // 0..31 -> 4 d-cols each
    int numTiles = (kLen + 15) >> 4;

    uint32_t xsA = (uint32_t)__cvta_generic_to_shared(&xs[0][0]);
    uint32_t wsA = (uint32_t)__cvta_generic_to_shared(&ws[0][0]);

    auto issueTile = [&](int t) {
        if (t < numTiles) {
            int k0 = t << 4;
            int s  = t % 3;
            #pragma unroll
            for (int j = 0; j < 4; j++) {
                int i = tid + j * 256;
                int b = i >> 4, kk = i & 15;
                int gk = k0 + kk;
                int sz = (gk < kLen) ? 4 : 0;
                const float* src = X + b * NPIX + pSm[gk];
                uint32_t dst = xsA + (uint32_t)(s * (16 * 68) + kk * 68 + b) * 4u;
                CP4(dst, src, sz);
            }
            #pragma unroll
            for (int j = 0; j < 8; j++) {
                int i = tid + j * 256;
                int d = i >> 4, kk = i & 15;
                int gk = k0 + kk;
                int sz = (gk < kLen) ? 4 : 0;
                const float* src = W + (size_t)(d0 + d) * NPIX + pSm[gk];
                uint32_t dst = wsA + (uint32_t)(s * (16 * 132) + kk * 132 + d) * 4u;
                CP4(dst, src, sz);
            }
        }
        CP_COMMIT();
    };

    unsigned long long acc[4][4];     // [b-pair][d]
    #pragma unroll
    for (int i = 0; i < 4; i++)
        #pragma unroll
        for (int j = 0; j < 4; j++) acc[i][j] = 0ULL;

    issueTile(0);
    issueTile(1);

    for (int t = 0; t < numTiles; t++) {
        CP_WAIT1();                 // tile t resident (t+1 may be in flight)
        __syncthreads();            // all warps see it; stage (t-1)%3 free
        issueTile(t + 2);           // refill stage (t+2)%3 == (t-1)%3

        int s = t % 3;
        const float* xb = &xs[s][0];
        const float* wb = &ws[s][0];
        #pragma unroll
        for (int kk = 0; kk < 16; kk++) {
            const float* xrow = xb + kk * 68 + tb * 8;
            ulonglong2 xa = *(const ulonglong2*)xrow;         // b-pairs 0,1
            ulonglong2 xc = *(const ulonglong2*)(xrow + 4);   // b-pairs 2,3
            float4 wv = *(const float4*)(wb + kk * 132 + td * 4);
            unsigned long long wp0, wp1, wp2, wp3;
            PACK2(wp0, wv.x); PACK2(wp1, wv.y); PACK2(wp2, wv.z); PACK2(wp3, wv.w);
            FMA2(acc[0][0], xa.x, wp0); FMA2(acc[0][1], xa.x, wp1);
            FMA2(acc[0][2], xa.x, wp2); FMA2(acc[0][3], xa.x, wp3);
            FMA2(acc[1][0], xa.y, wp0); FMA2(acc[1][1], xa.y, wp1);
            FMA2(acc[1][2], xa.y, wp2); FMA2(acc[1][3], xa.y, wp3);
            FMA2(acc[2][0], xc.x, wp0); FMA2(acc[2][1], xc.x, wp1);
            FMA2(acc[2][2], xc.x, wp2); FMA2(acc[2][3], xc.x, wp3);
            FMA2(acc[3][0], xc.y, wp0); FMA2(acc[3][1], xc.y, wp1);
            FMA2(acc[3][2], xc.y, wp2); FMA2(acc[3][3], xc.y, wp3);
        }
    }

    // unpack + write partials (float4 per b-row)
    size_t base = (size_t)ch * (NB * ND);
    #pragma unroll
    for (int bp = 0; bp < 4; bp++) {
        float lo0, hi0, lo1, hi1, lo2, hi2, lo3, hi3;
        UNPACK2(lo0, hi0, acc[bp][0]);
        UNPACK2(lo1, hi1, acc[bp][1]);
        UNPACK2(lo2, hi2, acc[bp][2]);
        UNPACK2(lo3, hi3, acc[bp][3]);
        int b0 = tb * 8 + bp * 2;
        float4 vlo = make_float4(lo0, lo1, lo2, lo3);
        float4 vhi = make_float4(hi0, hi1, hi2, hi3);
        *(float4*)&g_partial[base + (size_t)b0 * ND + d0 + td * 4] = vlo;
        *(float4*)&g_partial[base + (size_t)(b0 + 1) * ND + d0 + td * 4] = vhi;
    }
}

// ------------------------- 4) parallel chunk reduction ---------------------
// Grid (64 b, 16 rings), 256 threads (one per d). 4-way MLP over chunks.
__global__ void __launch_bounds__(256)
k_reduce() {
    int b = blockIdx.x, c = blockIdx.y, tid = threadIdx.x;
    int c0 = g_ringChunkStart[c], c1 = g_ringChunkStart[c + 1];
    size_t brow = (size_t)b * ND + tid;
    float s0 = 0.f, s1 = 0.f, s2 = 0.f, s3 = 0.f;
    int ch = c0;
    for (; ch + 3 < c1; ch += 4) {
        s0 += g_partial[(size_t)ch * (NB * ND) + brow];
        s1 += g_partial[(size_t)(ch + 1) * (NB * ND) + brow];
        s2 += g_partial[(size_t)(ch + 2) * (NB * ND) + brow];
        s3 += g_partial[(size_t)(ch + 3) * (NB * ND) + brow];
    }
    for (; ch < c1; ch++) s0 += g_partial[(size_t)ch * (NB * ND) + brow];
    g_tok[((size_t)b * 16 + c) * ND + tid] = (s0 + s1) + (s2 + s3);
}

// ------------------------- 5) fc projection (256->192) ---------------------
// Grid 64 (one block per b), 256 threads (192 compute).
__global__ void __launch_bounds__(256)
k_fc(const float* __restrict__ fcw, const float* __restrict__ fcb,
     float* __restrict__ out) {
    __shared__ __align__(16) float tok[256 * 20];   // [d][c] padded to 20

    int b = blockIdx.x, tid = threadIdx.x;
    for (int i = tid; i < 16 * ND; i += 256) {
        int c = i >> 8, d = i & 255;
        tok[d * 20 + c] = g_tok[((size_t)b * 16 + c) * ND + d];
    }
    __syncthreads();

    if (tid < 192) {
        int j = tid;
        unsigned long long acc[8];
        #pragma unroll
        for (int q = 0; q < 8; q++) acc[q] = 0ULL;

        const float4* fw4 = (const float4*)(fcw + (size_t)j * ND);
        #pragma unroll 4
        for (int d4 = 0; d4 < 64; d4++) {
            float4 wv = fw4[d4];
            #pragma unroll
            for (int s = 0; s < 4; s++) {
                int d = d4 * 4 + s;
                float w = (s == 0) ? wv.x : (s == 1) ? wv.y : (s == 2) ? wv.z : wv.w;
                unsigned long long wp;
                PACK2(wp, w);
                const ulonglong2* tp = (const ulonglong2*)&tok[d * 20];
                ulonglong2 t0 = tp[0], t1 = tp[1], t2 = tp[2], t3 = tp[3];
                FMA2(acc[0], t0.x, wp); FMA2(acc[1], t0.y, wp);
                FMA2(acc[2], t1.x, wp); FMA2(acc[3], t1.y, wp);
                FMA2(acc[4], t2.x, wp); FMA2(acc[5], t2.y, wp);
                FMA2(acc[6], t3.x, wp); FMA2(acc[7], t3.y, wp);
            }
        }
        float bias = fcb[j];
        #pragma unroll
        for (int q = 0; q < 8; q++) {
            float lo, hi;
            UNPACK2(lo, hi, acc[q]);
            out[((size_t)b * 16 + 2 * q) * 192 + j]     = lo + bias;
            out[((size_t)b * 16 + 2 * q + 1) * 192 + j] = hi + bias;
        }
    }
}

// ---------------------------------------------------------------------------
extern "C" void kernel_launch(void* const* d_in, const int* in_sizes, int n_in,
                              void* d_out, int out_size) {
    const float* x   = (const float*)d_in[0];  // [64, 224, 224]
    const float* tw  = (const float*)d_in[1];  // [256, 1, 224, 224]
    const float* fcw = (const float*)d_in[2];  // [192, 256]
    const float* fcb = (const float*)d_in[3];  // [192]
    // d_in[4] (masks) unused: rings derived analytically (exact).
    float* out = (float*)d_out;                // [64, 16, 192]

    k_prep<<<1, 256>>>();
    k_scatter<<<14, 256>>>();
    k_gemm<<<dim3(MAXC, 2), 256>>>(x, tw);
    k_reduce<<<dim3(64, 16), 256>>>();
    k_fc<<<64, 256>>>(fcw, fcb, out);
}